// round 16
// baseline (speedup 1.0000x reference)
#include <cuda_runtime.h>
#include <cuda_bf16.h>
#include <cuda_fp16.h>
#include <cstdint>
#include <math.h>

#define T_LEN   8192
#define B_SZ    2
#define N_HEADS 8
#define DH      128
#define EMB     1024
#define BHD     16          // B * HEADS
#define N_HASH  8
#define NB      128         // buckets per hash
#define NBTOT   1024        // N_HASH * NB
#define BUCKETSZ 64
#define NCHUNK  1024        // per bh
#define HT      65536       // N_HASH * T
#define BT      16384       // B * T
#define QSCALE  0.08838834764831843f
#define FIX_CAP (1 << 20)
#define MARGIN_TH 4e-3f
#define SEGSZ   512
#define NSEG    16          // T_LEN / SEGSZ

// ----------------------------- scratch (static device memory; no allocs) ---
__device__ __half g_x_hi[(size_t)BT * EMB];
__device__ __half g_x_lo[(size_t)BT * EMB];
__device__ __half g_qk_hi[(size_t)BT * EMB];        // fp16 pairs (rv GEMM + prep)
__device__ __half g_qk_lo[(size_t)BT * EMB];
__device__ __nv_bfloat16 g_k_hi[(size_t)BT * EMB];  // normalized k (attention)
__device__ __nv_bfloat16 g_k_lo[(size_t)BT * EMB];
__device__ float g_qscale[(size_t)BT * N_HEADS];    // QSCALE * ||qk_row||
__device__ __nv_bfloat16 g_v_hi[(size_t)BT * EMB];  // v pairs (from GEMM epilogue)
__device__ __nv_bfloat16 g_v_lo[(size_t)BT * EMB];
__device__ __half g_attn_hi[(size_t)BT * EMB];
__device__ __half g_attn_lo[(size_t)BT * EMB];
__device__ __half g_wqkT_hi[EMB * EMB];
__device__ __half g_wqkT_lo[EMB * EMB];
__device__ __half g_wvT_hi[EMB * EMB];
__device__ __half g_wvT_lo[EMB * EMB];
__device__ __half g_woutT_hi[EMB * EMB];
__device__ __half g_woutT_lo[EMB * EMB];
__device__ __half g_rotT_hi[512 * DH];
__device__ __half g_rotT_lo[512 * DH];
__device__ float g_rv[(size_t)BHD * T_LEN * 512];
__device__ int   g_buckets[(size_t)BHD * HT];
__device__ int   g_counts[BHD * NBTOT];
__device__ int   g_offsets[BHD * NBTOT];
__device__ int   g_segcnt[BHD * N_HASH * NSEG * NB];   // 1 MB
__device__ int   g_segbase[BHD * N_HASH * NSEG * NB];  // 1 MB
__device__ int   g_st[(size_t)BHD * HT];
__device__ int   g_undo[(size_t)BHD * HT];
__device__ int   g_fixn;
__device__ int   g_fixlist[FIX_CAP];
__device__ __half g_so_h[(size_t)BHD * HT * DH];    // fp16 attention outputs
__device__ float g_slog[(size_t)BHD * HT];

// ----------------------------- cp.async helpers -----------------------------
__device__ __forceinline__ void cp_async16(uint32_t dst, const void* src) {
    asm volatile("cp.async.ca.shared.global [%0], [%1], 16;" :: "r"(dst), "l"(src));
}
#define CP_COMMIT() asm volatile("cp.async.commit_group;" ::: "memory")
#define CP_WAIT(n)  asm volatile("cp.async.wait_group %0;" :: "n"(n) : "memory")

// ----------------------------- mma helpers (portable PTX, sm_80+) ----------
__device__ __forceinline__ uint32_t smem_u32(const void* p) {
    uint32_t a;
    asm("{ .reg .u64 t; cvta.to.shared.u64 t, %1; cvt.u32.u64 %0, t; }" : "=r"(a) : "l"(p));
    return a;
}
__device__ __forceinline__ void ldm_x4(uint32_t* r, uint32_t addr) {
    asm volatile("ldmatrix.sync.aligned.m8n8.x4.shared.b16 {%0,%1,%2,%3}, [%4];"
        : "=r"(r[0]), "=r"(r[1]), "=r"(r[2]), "=r"(r[3]) : "r"(addr));
}
__device__ __forceinline__ void ldm_x4_t(uint32_t* r, uint32_t addr) {
    asm volatile("ldmatrix.sync.aligned.m8n8.x4.trans.shared.b16 {%0,%1,%2,%3}, [%4];"
        : "=r"(r[0]), "=r"(r[1]), "=r"(r[2]), "=r"(r[3]) : "r"(addr));
}
__device__ __forceinline__ void ldm_x2(uint32_t* r, uint32_t addr) {
    asm volatile("ldmatrix.sync.aligned.m8n8.x2.shared.b16 {%0,%1}, [%2];"
        : "=r"(r[0]), "=r"(r[1]) : "r"(addr));
}
__device__ __forceinline__ void mma16816(float* d, const uint32_t* a, const uint32_t* b) {
    asm volatile("mma.sync.aligned.m16n8k16.row.col.f32.bf16.bf16.f32 "
        "{%0,%1,%2,%3}, {%4,%5,%6,%7}, {%8,%9}, {%0,%1,%2,%3};"
        : "+f"(d[0]), "+f"(d[1]), "+f"(d[2]), "+f"(d[3])
        : "r"(a[0]), "r"(a[1]), "r"(a[2]), "r"(a[3]), "r"(b[0]), "r"(b[1]));
}
__device__ __forceinline__ void mma16816h(float* d, const uint32_t* a, const uint32_t* b) {
    asm volatile("mma.sync.aligned.m16n8k16.row.col.f32.f16.f16.f32 "
        "{%0,%1,%2,%3}, {%4,%5,%6,%7}, {%8,%9}, {%0,%1,%2,%3};"
        : "+f"(d[0]), "+f"(d[1]), "+f"(d[2]), "+f"(d[3])
        : "r"(a[0]), "r"(a[1]), "r"(a[2]), "r"(a[3]), "r"(b[0]), "r"(b[1]));
}
__device__ __forceinline__ uint32_t packbf2(float x, float y) {
    __nv_bfloat162 p(__float2bfloat16_rn(x), __float2bfloat16_rn(y));
    return *(uint32_t*)&p;
}

// ----------------------------- fp16-split tensor-core GEMM (pipelined) ------
// C[M,N] = A[M,K] @ B^T (B stored [N][K]); A,B fp16 (hi,lo) pairs, 3 terms.
// 3-stage cp.async pipeline; BK=64; 192KB dynamic smem; one sync per chunk.
// Pair output: bf16pair=0 -> fp16 pairs; 1 -> bf16 pairs. C may be null.
#define SA_HI 0
#define SA_LO 16384
#define SB_HI 32768
#define SB_LO 49152
#define STAGE_STRIDE 65536
#define GEMM_SMEM 196608

__global__ void __launch_bounds__(256) mma_gemm_h(
    const __half* __restrict__ Ahi, const __half* __restrict__ Alo,
    const __half* __restrict__ Bhi, const __half* __restrict__ Blo,
    float* __restrict__ C, const float* __restrict__ bias,
    __half* __restrict__ Chi, __half* __restrict__ Clo, int bf16pair,
    int K, int lda, int ldb, int ldc,
    long long sAouter, long long sAinner, int innerDiv,
    long long sB, long long sC)
{
    extern __shared__ char sm[];
    uint32_t sb = smem_u32(sm);
    int tid = threadIdx.x, lane = tid & 31, wid = tid >> 5;
    int wm = wid & 1, wn = wid >> 1;

    long long z = blockIdx.z;
    size_t aoff = (size_t)((z / innerDiv) * sAouter + (z % innerDiv) * sAinner);
    const __half* Ah = Ahi + aoff;
    const __half* Al = Alo + aoff;
    const __half* Bh = Bhi + (size_t)(z * sB);
    const __half* Bl = Blo + (size_t)(z * sB);
    int m0 = blockIdx.y * 128, n0 = blockIdx.x * 128;

    float acc[4][4][4];
#pragma unroll
    for (int mt = 0; mt < 4; mt++)
#pragma unroll
        for (int nt = 0; nt < 4; nt++)
#pragma unroll
            for (int i = 0; i < 4; i++) acc[mt][nt][i] = 0.f;

    int nch = K >> 6;

    auto issue = [&](int ch) {
        int k0 = ch << 6;
        uint32_t stg = sb + (uint32_t)((ch % 3) * STAGE_STRIDE);
        const __half* Abh = Ah + (size_t)m0 * lda + k0;
        const __half* Abl = Al + (size_t)m0 * lda + k0;
        const __half* Bbh = Bh + (size_t)n0 * ldb + k0;
        const __half* Bbl = Bl + (size_t)n0 * ldb + k0;
#pragma unroll
        for (int i = 0; i < 4; i++) {
            int idx = tid + (i << 8);
            int row = idx >> 3, seg = idx & 7;
            uint32_t off = (uint32_t)((row << 7) + (seg << 4));
            uint32_t sw = off ^ ((off >> 3) & 0x70);
            cp_async16(stg + SA_HI + sw, Abh + (size_t)row * lda + (seg << 3));
            cp_async16(stg + SA_LO + sw, Abl + (size_t)row * lda + (seg << 3));
            cp_async16(stg + SB_HI + sw, Bbh + (size_t)row * ldb + (seg << 3));
            cp_async16(stg + SB_LO + sw, Bbl + (size_t)row * ldb + (seg << 3));
        }
        CP_COMMIT();
    };

    issue(0);
    if (nch > 1) issue(1);
    for (int ch = 0; ch < nch; ch++) {
        if (ch + 1 < nch) { CP_WAIT(1); } else { CP_WAIT(0); }
        __syncthreads();            // ch's data visible; ch-1 reads done block-wide
        if (ch + 2 < nch) issue(ch + 2);   // refills stage (ch-1)%3, safe after sync
        uint32_t stg = sb + (uint32_t)((ch % 3) * STAGE_STRIDE);
#pragma unroll
        for (int kk = 0; kk < 4; kk++) {
            uint32_t afh[4][4], afl[4][4];
#pragma unroll
            for (int mt = 0; mt < 4; mt++) {
                int row = wm * 64 + mt * 16 + (lane & 15);
                uint32_t off = (uint32_t)((row << 7) + (kk << 5) + ((lane >> 4) << 4));
                uint32_t sw = off ^ ((off >> 3) & 0x70);
                ldm_x4(afh[mt], stg + SA_HI + sw);
                ldm_x4(afl[mt], stg + SA_LO + sw);
            }
            uint32_t bfh[4][2], bfl[4][2];
#pragma unroll
            for (int nt = 0; nt < 4; nt++) {
                int row = wn * 32 + nt * 8 + (lane & 7);
                uint32_t off = (uint32_t)((row << 7) + (kk << 5) + (((lane >> 3) & 1) << 4));
                uint32_t sw = off ^ ((off >> 3) & 0x70);
                ldm_x2(bfh[nt], stg + SB_HI + sw);
                ldm_x2(bfl[nt], stg + SB_LO + sw);
            }
#pragma unroll
            for (int mt = 0; mt < 4; mt++)
#pragma unroll
                for (int nt = 0; nt < 4; nt++) {
                    mma16816h(acc[mt][nt], afh[mt], bfh[nt]);
                    mma16816h(acc[mt][nt], afh[mt], bfl[nt]);
                    mma16816h(acc[mt][nt], afl[mt], bfh[nt]);
                }
        }
    }
    __syncthreads();

    float* Cb = C ? (C + (size_t)(z * sC)) : nullptr;
#pragma unroll
    for (int mt = 0; mt < 4; mt++) {
#pragma unroll
        for (int nt = 0; nt < 4; nt++) {
            int c = n0 + wn * 32 + nt * 8 + ((lane & 3) << 1);
#pragma unroll
            for (int hf = 0; hf < 2; hf++) {
                int r = m0 + wm * 64 + mt * 16 + (lane >> 2) + hf * 8;
                float v0 = acc[mt][nt][hf * 2 + 0];
                float v1 = acc[mt][nt][hf * 2 + 1];
                if (bias) { v0 += bias[c]; v1 += bias[c + 1]; }
                size_t off = (size_t)r * ldc + c;
                if (Cb) *(float2*)(Cb + off) = make_float2(v0, v1);
                if (Chi) {
                    if (bf16pair) {
                        float h0 = __bfloat162float(__float2bfloat16_rn(v0));
                        float h1 = __bfloat162float(__float2bfloat16_rn(v1));
                        *(uint32_t*)(Chi + off) = packbf2(v0, v1);
                        *(uint32_t*)(Clo + off) = packbf2(v0 - h0, v1 - h1);
                    } else {
                        __half h0 = __float2half_rn(v0);
                        __half h1 = __float2half_rn(v1);
                        *(__half2*)(Chi + off) = __half2(h0, h1);
                        *(__half2*)(Clo + off) = __half2(
                            __float2half_rn(v0 - __half2float(h0)),
                            __float2half_rn(v1 - __half2float(h1)));
                    }
                }
            }
        }
    }
}

// ----------------------------- conversions ----------------------------------
__global__ void convert_pair_kernel(const float* __restrict__ src,
                                    __half* __restrict__ hi,
                                    __half* __restrict__ lo, int n)
{
    int i = blockIdx.x * 256 + threadIdx.x;
    if (i < n) {
        float v = src[i];
        __half h = __float2half_rn(v);
        hi[i] = h;
        lo[i] = __float2half_rn(v - __half2float(h));
    }
}

__global__ void transpose_pair_kernel(const float* __restrict__ src,
                                      __half* __restrict__ dhi,
                                      __half* __restrict__ dlo, int R, int C)
{
    __shared__ float t[32][33];
    int c0 = blockIdx.x * 32, r0 = blockIdx.y * 32;
    int x = threadIdx.x, y = threadIdx.y;
    for (int i = 0; i < 32; i += 8)
        t[y + i][x] = src[(size_t)(r0 + y + i) * C + c0 + x];
    __syncthreads();
    for (int i = 0; i < 32; i += 8) {
        float v = t[x][y + i];
        __half h = __float2half_rn(v);
        size_t o = (size_t)(c0 + y + i) * R + r0 + x;
        dhi[o] = h;
        dlo[o] = __float2half_rn(v - __half2float(h));
    }
}

// ----------------------------- k-hat + qscale precompute --------------------
__global__ void prep_qk_kernel()
{
    int gw = (blockIdx.x * 256 + threadIdx.x) >> 5;    // 0..BT*8-1
    int lane = threadIdx.x & 31;
    int h = gw & 7;
    int bt = gw >> 3;
    size_t base = (size_t)bt * EMB + h * DH;
    uint2 uh = *(const uint2*)(g_qk_hi + base + lane * 4);
    uint2 ul = *(const uint2*)(g_qk_lo + base + lane * 4);
    __half2 h01 = *(__half2*)&uh.x, h23 = *(__half2*)&uh.y;
    __half2 l01 = *(__half2*)&ul.x, l23 = *(__half2*)&ul.y;
    float v0 = __half2float(h01.x) + __half2float(l01.x);
    float v1 = __half2float(h01.y) + __half2float(l01.y);
    float v2 = __half2float(h23.x) + __half2float(l23.x);
    float v3 = __half2float(h23.y) + __half2float(l23.y);
    float ss = v0 * v0 + v1 * v1 + v2 * v2 + v3 * v3;
#pragma unroll
    for (int o = 16; o > 0; o >>= 1) ss += __shfl_xor_sync(0xffffffffu, ss, o);
    float sq = sqrtf(fmaxf(ss, 1e-12f));
    float rn = 1.0f / sq;
    float k0v = v0 * rn, k1v = v1 * rn, k2v = v2 * rn, k3v = v3 * rn;
    float kh0 = __bfloat162float(__float2bfloat16_rn(k0v));
    float kh1 = __bfloat162float(__float2bfloat16_rn(k1v));
    float kh2 = __bfloat162float(__float2bfloat16_rn(k2v));
    float kh3 = __bfloat162float(__float2bfloat16_rn(k3v));
    size_t e = base + lane * 4;
    *(uint2*)(g_k_hi + e) = make_uint2(packbf2(k0v, k1v), packbf2(k2v, k3v));
    *(uint2*)(g_k_lo + e) = make_uint2(packbf2(k0v - kh0, k1v - kh1), packbf2(k2v - kh2, k3v - kh3));
    if (lane == 0) g_qscale[(size_t)bt * N_HEADS + h] = QSCALE * sq;
}

// ----------------------------- bucket argmax + margin guard -----------------
__global__ void bucket_kernel()
{
    int idx = blockIdx.x * 256 + threadIdx.x;
    int h = idx & 7;
    int t = (idx >> 3) & (T_LEN - 1);
    int bh = idx >> 16;
    const float4* p = (const float4*)(g_rv + ((size_t)bh * T_LEN + t) * 512 + h * 64);
    float max1 = -1e30f, max2 = -1e30f, min1 = 1e30f, min2 = 1e30f;
    int imax = 0, imin = 0;
#pragma unroll
    for (int i = 0; i < 16; i++) {
        float4 q = p[i];
        float vv[4] = {q.x, q.y, q.z, q.w};
#pragma unroll
        for (int c = 0; c < 4; c++) {
            int j = i * 4 + c;
            float v = vv[c];
            if (v > max1) { max2 = max1; max1 = v; imax = j; }
            else if (v > max2) max2 = v;
            if (v < min1) { min2 = min1; min1 = v; imin = j; }
            else if (v < min2) min2 = v;
        }
    }
    float best, second;
    int bi;
    if (max1 >= -min1) { best = max1; bi = imax; second = fmaxf(max2, -min1); }
    else               { best = -min1; bi = 64 + imin; second = fmaxf(max1, -min2); }
    g_buckets[(size_t)bh * HT + (size_t)h * T_LEN + t] = bi + h * NB;
    if (best - second < MARGIN_TH) {
        int slot = atomicAdd(&g_fixn, 1);
        if (slot < FIX_CAP)
            g_fixlist[slot] = (bh << 16) | (h * T_LEN + t);
    }
}

// full exact recompute of flagged rows (sequential fp32 from x, Wqk, rot)
__global__ void fixup_kernel(const float* __restrict__ x,
                             const float* __restrict__ Wqk,
                             const float* __restrict__ rot)
{
    __shared__ float qrow_s[8][128];
    int wslot = threadIdx.x >> 5;
    int lane = threadIdx.x & 31;
    int gw = blockIdx.x * 8 + wslot;
    int nwarps = gridDim.x * 8;
    int n = g_fixn;
    if (n > FIX_CAP) n = FIX_CAP;
    for (int e = gw; e < n; e += nwarps) {
        int ent = g_fixlist[e];
        int bh = ent >> 16;
        int ht = ent & 65535;
        int h = ht >> 13, t = ht & (T_LEN - 1);
        int b = bh >> 3, hh = bh & 7;
        const float* xrow = x + (size_t)(b * T_LEN + t) * EMB;
        float a0 = 0.f, a1 = 0.f, a2 = 0.f, a3 = 0.f;
        for (int k = 0; k < EMB; k++) {
            float xv = xrow[k];
            const float* wr = Wqk + (size_t)k * EMB + hh * DH;
            a0 = fmaf(xv, wr[lane], a0);
            a1 = fmaf(xv, wr[lane + 32], a1);
            a2 = fmaf(xv, wr[lane + 64], a2);
            a3 = fmaf(xv, wr[lane + 96], a3);
        }
        qrow_s[wslot][lane] = a0;
        qrow_s[wslot][lane + 32] = a1;
        qrow_s[wslot][lane + 64] = a2;
        qrow_s[wslot][lane + 96] = a3;
        __syncwarp();
        int c1 = lane, c2 = lane + 32;
        float r1 = 0.f, r2 = 0.f;
        for (int k = 0; k < DH; k++) {
            float a = qrow_s[wslot][k];
            const float* rp = rot + ((size_t)k * 8 + h) * 64;
            r1 = fmaf(a, rp[c1], r1);
            r2 = fmaf(a, rp[c2], r2);
        }
        float best = r1; int bi = c1;
        if (r2 > best)  { best = r2;  bi = c2; }
        if (-r1 > best) { best = -r1; bi = 64 + c1; }
        if (-r2 > best) { best = -r2; bi = 64 + c2; }
#pragma unroll
        for (int o = 16; o > 0; o >>= 1) {
            float ov = __shfl_xor_sync(0xffffffffu, best, o);
            int oi = __shfl_xor_sync(0xffffffffu, bi, o);
            if (ov > best || (ov == best && oi < bi)) { best = ov; bi = oi; }
        }
        if (lane == 0)
            g_buckets[(size_t)bh * HT + (size_t)h * T_LEN + t] = bi + h * NB;
        __syncwarp();
    }
}

__global__ void zero_fixn_kernel() { g_fixn = 0; }

// ----------------------------- segmented stable counting sort ---------------
// per-(bh, h, 512-token segment) histogram (one warp each)
__global__ void segcount_kernel()
{
    __shared__ int hist[8][NB];
    int w = threadIdx.x >> 5, lane = threadIdx.x & 31;
    int gw = blockIdx.x * 8 + w;               // 0..BHD*8*NSEG-1
    int seg = gw & (NSEG - 1);
    int h = (gw >> 4) & 7;
    int bh = gw >> 7;
    for (int i = lane; i < NB; i += 32) hist[w][i] = 0;
    __syncwarp();
    const int* bk = g_buckets + (size_t)bh * HT + (size_t)h * T_LEN + seg * SEGSZ;
    for (int t0 = 0; t0 < SEGSZ; t0 += 32)
        atomicAdd(&hist[w][bk[t0 + lane] - h * NB], 1);
    __syncwarp();
    int* dst = g_segcnt + (((bh * 8 + h) * NSEG) + seg) * NB;
    for (int i = lane; i < NB; i += 32) dst[i] = hist[w][i];
}

// counts[bh][gb] = sum over segments
__global__ void sumcnt_kernel()
{
    int idx = blockIdx.x * 256 + threadIdx.x;  // 0..BHD*NBTOT-1
    int bh = idx >> 10, gb = idx & 1023;
    const int* sc = g_segcnt + ((bh * 8 + (gb >> 7)) * NSEG) * NB + (gb & 127);
    int s = 0;
#pragma unroll
    for (int i = 0; i < NSEG; i++) s += sc[i * NB];
    g_counts[bh * NBTOT + gb] = s;
}

__global__ void scan_kernel()
{
    __shared__ int s[NBTOT];
    int bh = blockIdx.x, t = threadIdx.x;
    int my = g_counts[bh * NBTOT + t];
    s[t] = my;
    __syncthreads();
    for (int d = 1; d < NBTOT; d <<= 1) {
        int v = (t >= d) ? s[t - d] : 0;
        __syncthreads();
        s[t] += v;
        __syncthreads();
    }
    g_offsets[bh * NBTOT + t] = s[t] - my;
}

// per-bucket prefix over segments: segbase = global offset + running seg sum
__global__ void segbase_kernel()
{
    int bh = blockIdx.x;
    int gb = threadIdx.x;                      // 0..1023
    int base = g_offsets[bh * NBTOT + gb];
    int h = gb >> 7, b = gb & 127;
    const int* sc = g_segcnt + ((bh * 8 + h) * NSEG) * NB + b;
    int* sbp = g_segbase + ((bh * 8 + h) * NSEG) * NB + b;
#pragma unroll
    for (int s = 0; s < NSEG; s++) {
        sbp[s * NB] = base;
        base += sc[s * NB];
    }
}

// parallel stable scatter: one warp per (bh, h, segment)
__global__ void scatter_seg_kernel()
{
    __shared__ int cnt[8][NB];
    int w = threadIdx.x >> 5, lane = threadIdx.x & 31;
    int gw = blockIdx.x * 8 + w;
    int seg = gw & (NSEG - 1);
    int h = (gw >> 4) & 7;
    int bh = gw >> 7;
    const int* sbp = g_segbase + (((bh * 8 + h) * NSEG) + seg) * NB;
    for (int i = lane; i < NB; i += 32) cnt[w][i] = sbp[i];
    __syncwarp();
    const int* bk = g_buckets + (size_t)bh * HT + (size_t)h * T_LEN;
    int* stp = g_st + (size_t)bh * HT;
    int* unp = g_undo + (size_t)bh * HT + (size_t)h * T_LEN;
    int tb = seg * SEGSZ;
    for (int t0 = tb; t0 < tb + SEGSZ; t0 += 32) {
        int t = t0 + lane;
        int b = bk[t] - h * NB;
        unsigned mask = __match_any_sync(0xffffffffu, b);
        int lead = __ffs(mask) - 1;
        int pre = __popc(mask & ((1u << lane) - 1u));
        int base = 0;
        if (lane == lead) base = cnt[w][b];
        base = __shfl_sync(0xffffffffu, base, lead);
        int rnk = base + pre;
        if (lane == lead) cnt[w][b] = base + __popc(mask);
        stp[rnk] = t;
        unp[t] = rnk;
        __syncwarp();
    }
}

// ----------------------------- tensor-core chunked attention ----------------
#define PT  136
#define OFF_KV_HI 0
#define OFF_KV_LO 34816
#define OFF_P_HI  69632
#define OFF_P_LO  87040
#define OFF_REDM  104448
#define OFF_REDS  104960
#define OFF_POS   105472
#define OFF_PAD   105984
#define OFF_SCL   106496
#define SMEM_ATT  106752

__global__ void __launch_bounds__(256, 2) attn_kernel(const unsigned char* __restrict__ pm)
{
    extern __shared__ char sm[];
    uint32_t sb = smem_u32(sm);
    __nv_bfloat16* phi = (__nv_bfloat16*)(sm + OFF_P_HI);
    __nv_bfloat16* plo = (__nv_bfloat16*)(sm + OFF_P_LO);
    float* redM = (float*)(sm + OFF_REDM);
    float* redS = (float*)(sm + OFF_REDS);
    int* posk = (int*)(sm + OFF_POS);
    int* padk = (int*)(sm + OFF_PAD);
    float* sclb = (float*)(sm + OFF_SCL);

    int bh = blockIdx.y, c = blockIdx.x;
    int b = bh >> 3, h = bh & 7;
    int tid = threadIdx.x, lane = tid & 31, wid = tid >> 5;

    if (tid < 128) {
        int j = tid;
        int cprev = (c == 0) ? (NCHUNK - 1) : (c - 1);
        int slot = (j < BUCKETSZ) ? c * BUCKETSZ + j : cprev * BUCKETSZ + (j - BUCKETSZ);
        int pos = g_st[(size_t)bh * HT + slot];
        posk[j] = pos;
        padk[j] = pm[b * T_LEN + pos] ? 1 : 0;
        if (j < 64) sclb[j] = g_qscale[(size_t)(b * T_LEN + pos) * N_HEADS + h];
    }
    __syncthreads();

    // phase 1: cp.async gather of k-hat pairs (128 rows)
    for (int i = tid; i < 2048; i += 256) {
        int r = i >> 4, ck = i & 15;
        int pos = posk[r];
        size_t so = (size_t)(b * T_LEN + pos) * EMB + h * DH + (ck << 3);
        uint32_t d = (uint32_t)((r * PT + (ck << 3)) * 2);
        cp_async16(sb + OFF_KV_HI + d, g_k_hi + so);
        cp_async16(sb + OFF_KV_LO + d, g_k_lo + so);
    }
    CP_COMMIT();
    CP_WAIT(0);
    __syncthreads();

    // phase 2: S[64][128] = (k-hat_q @ k-hat_kv^T) * scale_q
    int mt = wid & 3, nh = wid >> 2;
    float cS[8][4];
#pragma unroll
    for (int i = 0; i < 8; i++)
#pragma unroll
        for (int j = 0; j < 4; j++) cS[i][j] = 0.f;
    {
        uint32_t g = lane >> 3, i2 = lane & 7;
#pragma unroll
        for (int ks = 0; ks < 8; ks++) {
            int k0 = ks * 16;
            uint32_t ah[4], al[4];
            uint32_t aoff = (uint32_t)(((mt * 16 + (lane & 15)) * PT + k0 + ((lane >> 4) << 3)) * 2);
            ldm_x4(ah, sb + OFF_KV_HI + aoff);
            ldm_x4(al, sb + OFF_KV_LO + aoff);
#pragma unroll
            for (int np = 0; np < 4; np++) {
                int n0 = nh * 64 + np * 16;
                uint32_t boff = (uint32_t)(((n0 + ((g >> 1) << 3) + i2) * PT + k0 + ((g & 1) << 3)) * 2);
                uint32_t bh4[4], bl4[4];
                ldm_x4(bh4, sb + OFF_KV_HI + boff);
                ldm_x4(bl4, sb + OFF_KV_LO + boff);
                mma16816(cS[np * 2], ah, bh4);
                mma16816(cS[np * 2], ah, bl4);
                mma16816(cS[np * 2], al, bh4);
                mma16816(cS[np * 2 + 1], ah, bh4 + 2);
                mma16816(cS[np * 2 + 1], ah, bl4 + 2);
                mma16816(cS[np * 2 + 1], al, bh4 + 2);
            }
        }
    }

    int q0 = mt * 16 + (lane >> 2);
    {
        float scl0 = sclb[q0], scl1 = sclb[q0 + 8];
        int pq0 = posk[q0], pq1 = posk[q0 + 8];
#pragma unroll
        for (int t8 = 0; t8 < 8; t8++) {
            int kvb = nh * 64 + t8 * 8 + ((lane & 3) << 1);
#pragma unroll
            for (int e = 0; e < 2; e++) {
                int kv = kvb + e;
                int pk = posk[kv], pd = padk[kv];
                float s0 = cS[t8][e] * scl0;
                float s1 = cS[t8][2 + e] * scl1;
                cS[t8][e]     = (pq0 == pk) ? -1e5f : (pd ? -1e9f : s0);
                cS[t8][2 + e] = (pq1 == pk) ? -1e5f : (pd ? -1e9f : s1);
            }
        }
    }

    // phase 3: softmax via e = exp(s - M); scale by 1/Z in the PV epilogue
    float rZA, rZB;
    {
        float mA = -1e30f, mB = -1e30f;
#pragma unroll
        for (int t8 = 0; t8 < 8; t8++) {
            mA = fmaxf(mA, fmaxf(cS[t8][0], cS[t8][1]));
            mB = fmaxf(mB, fmaxf(cS[t8][2], cS[t8][3]));
        }
        mA = fmaxf(mA, __shfl_xor_sync(0xffffffffu, mA, 1));
        mA = fmaxf(mA, __shfl_xor_sync(0xffffffffu, mA, 2));
        mB = fmaxf(mB, __shfl_xor_sync(0xffffffffu, mB, 1));
        mB = fmaxf(mB, __shfl_xor_sync(0xffffffffu, mB, 2));
        if ((lane & 3) == 0) {
            redM[q0 * 2 + nh] = mA;
            redM[(q0 + 8) * 2 + nh] = mB;
        }
        __syncthreads();       // all KV-buffer reads complete block-wide

        // V gather into kv buffers (overlaps exp below)
        for (int i = tid; i < 2048; i += 256) {
            int r = i >> 4, ck = i & 15;
            int pos = posk[r];
            size_t so = (size_t)(b * T_LEN + pos) * EMB + h * DH + (ck << 3);
            uint32_t d = (uint32_t)((r * PT + (ck << 3)) * 2);
            cp_async16(sb + OFF_KV_HI + d, g_v_hi + so);
            cp_async16(sb + OFF_KV_LO + d, g_v_lo + so);
        }
        CP_COMMIT();

        float MA = fmaxf(redM[q0 * 2], redM[q0 * 2 + 1]);
        float MB = fmaxf(redM[(q0 + 8) * 2], redM[(q0 + 8) * 2 + 1]);
        float sA = 0.f, sB = 0.f;
#pragma unroll
        for (int t8 = 0; t8 < 8; t8++) {
            int col = nh * 64 + t8 * 8 + ((lane & 3) << 1);
            float eA0 = __expf(cS[t8][0] - MA), eA1 = __expf(cS[t8][1] - MA);
            float eB0 = __expf(cS[t8][2] - MB), eB1 = __expf(cS[t8][3] - MB);
            sA += eA0 + eA1;
            sB += eB0 + eB1;
            float hA0 = __bfloat162float(__float2bfloat16_rn(eA0));
            float hA1 = __bfloat162float(__float2bfloat16_rn(eA1));
            float hB0 = __bfloat162float(__float2bfloat16_rn(eB0));
            float hB1 = __bfloat162float(__float2bfloat16_rn(eB1));
            *(uint32_t*)(phi + q0 * PT + col) = packbf2(eA0, eA1);
            *(uint32_t*)(plo + q0 * PT + col) = packbf2(eA0 - hA0, eA1 - hA1);
            *(uint32_t*)(phi + (q0 + 8) * PT + col) = packbf2(eB0, eB1);
            *(uint32_t*)(plo + (q0 + 8) * PT + col) = packbf2(eB0 - hB0, eB1 - hB1);
        }
        sA += __shfl_xor_sync(0xffffffffu, sA, 1);
        sA += __shfl_xor_sync(0xffffffffu, sA, 2);
        sB += __shfl_xor_sync(0xffffffffu, sB, 1);
        sB += __shfl_xor_sync(0xffffffffu, sB, 2);
        if ((lane & 3) == 0) {
            redS[q0 * 2 + nh] = sA;
            redS[(q0 + 8) * 2 + nh] = sB;
        }
        __syncthreads();
        float ZA = redS[q0 * 2] + redS[q0 * 2 + 1];
        float ZB = redS[(q0 + 8) * 2] + redS[(q0 + 8) * 2 + 1];
        if (nh == 0 && (lane & 3) == 0) {
            g_slog[(size_t)bh * HT + c * BUCKETSZ + q0] = MA + __logf(ZA);
            g_slog[(size_t)bh * HT + c * BUCKETSZ + q0 + 8] = MB + __logf(ZB);
        }
        rZA = 1.0f / ZA;
        rZB = 1.0f / ZB;
    }
    CP_WAIT(0);          // V resident
    __syncthreads();     // e writes visible block-wide

    // phase 4: O[64][128] = (E @ V) / Z
    {
        int dh2 = nh;
        float cO[8][4];
#pragma unroll
        for (int i = 0; i < 8; i++)
#pragma unroll
            for (int j = 0; j < 4; j++) cO[i][j] = 0.f;

        uint32_t g = lane >> 3, i2 = lane & 7;
#pragma unroll
        for (int ks = 0; ks < 8; ks++) {
            int k0 = ks * 16;
            uint32_t ah[4], al[4];
            uint32_t aoff = (uint32_t)(((mt * 16 + (lane & 15)) * PT + k0 + ((lane >> 4) << 3)) * 2);
            ldm_x4(ah, sb + OFF_P_HI + aoff);
            ldm_x4(al, sb + OFF_P_LO + aoff);
#pragma unroll
            for (int dp = 0; dp < 4; dp++) {
                int d0 = dh2 * 64 + dp * 16;
                uint32_t boff = (uint32_t)(((k0 + ((g & 1) << 3) + i2) * PT + d0 + ((g >> 1) << 3)) * 2);
                uint32_t bh4[4], bl4[4];
                ldm_x4_t(bh4, sb + OFF_KV_HI + boff);
                ldm_x4_t(bl4, sb + OFF_KV_LO + boff);
                mma16816(cO[dp * 2], ah, bh4);
                mma16816(cO[dp * 2], ah, bl4);
                mma16816(cO[dp * 2], al, bh4);
                mma16816(cO[dp * 2 + 1], ah, bh4 + 2);
                mma16816(cO[dp * 2 + 1], ah, bl4 + 2);
                mma16816(cO[dp * 2 + 1], al, bh4 + 2);
            }
        }
        __half* base0 = g_so_h + ((size_t)bh * HT + c * BUCKETSZ + q0) * DH;
        __half* base1 = g_so_h + ((size_t)bh * HT + c * BUCKETSZ + q0 + 8) * DH;
#pragma unroll
        for (int t8 = 0; t8 < 8; t8++) {
            int d = dh2 * 64 + t8 * 8 + ((lane & 3) << 1);
            *(__half2*)(base0 + d) = __floats2half2_rn(cO[t8][0] * rZA, cO[t8][1] * rZA);
            *(__half2*)(base1 + d) = __floats2half2_rn(cO[t8][2] * rZB, cO[t8][3] * rZB);
        }
    }
}

// ----------------------------- combine hash rounds --------------------------
__global__ void combine_kernel()
{
    int gw = (blockIdx.x * 256 + threadIdx.x) >> 5;
    int lane = threadIdx.x & 31;
    int bh = gw >> 13;
    int pos = gw & (T_LEN - 1);
    int b = bh >> 3, hh = bh & 7;

    int s = 0;
    float l = -1e30f;
    if (lane < N_HASH) {
        s = g_undo[(size_t)bh * HT + (size_t)lane * T_LEN + pos];
        l = g_slog[(size_t)bh * HT + s];
    }
    float m = l;
#pragma unroll
    for (int o = 16; o > 0; o >>= 1) m = fmaxf(m, __shfl_xor_sync(0xffffffffu, m, o));
    float e = (lane < N_HASH) ? __expf(l - m) : 0.f;
    float Z = e;
#pragma unroll
    for (int o = 16; o > 0; o >>= 1) Z += __shfl_xor_sync(0xffffffffu, Z, o);

    float4 acc = make_float4(0.f, 0.f, 0.f, 0.f);
#pragma unroll
    for (int h2 = 0; h2 < N_HASH; h2++) {
        int sh = __shfl_sync(0xffffffffu, s, h2);
        float wv = __shfl_sync(0xffffffffu, e, h2) / Z;
        const __half2* row = (const __half2*)(g_so_h + ((size_t)bh * HT + sh) * DH);
        __half2 p0 = row[lane * 2], p1 = row[lane * 2 + 1];
        float2 f0 = __half22float2(p0), f1 = __half22float2(p1);
        acc.x = fmaf(wv, f0.x, acc.x);
        acc.y = fmaf(wv, f0.y, acc.y);
        acc.z = fmaf(wv, f1.x, acc.z);
        acc.w = fmaf(wv, f1.y, acc.w);
    }
    size_t off = ((size_t)(b * T_LEN + pos)) * EMB + hh * DH + lane * 4;
    float fv[4] = {acc.x, acc.y, acc.z, acc.w};
    __half hi[4]; float lo[4];
#pragma unroll
    for (int u = 0; u < 4; u++) { hi[u] = __float2half_rn(fv[u]); lo[u] = fv[u] - __half2float(hi[u]); }
    ((__half2*)(g_attn_hi + off))[0] = __half2(hi[0], hi[1]);
    ((__half2*)(g_attn_hi + off))[1] = __half2(hi[2], hi[3]);
    ((__half2*)(g_attn_lo + off))[0] = __half2(__float2half_rn(lo[0]), __float2half_rn(lo[1]));
    ((__half2*)(g_attn_lo + off))[1] = __half2(__float2half_rn(lo[2]), __float2half_rn(lo[3]));
}

// ----------------------------- launcher -------------------------------------
extern "C" void kernel_launch(void* const* d_in, const int* in_sizes, int n_in,
                              void* d_out, int out_size)
{
    const float* x = (const float*)d_in[0];
    const unsigned char* pm = (const unsigned char*)d_in[1];
    const float* rot = (const float*)d_in[2];
    const float* Wqk = (const float*)d_in[3];
    const float* Wv = (const float*)d_in[4];
    const float* Wout = (const float*)d_in[5];
    const float* bout = (const float*)d_in[6];
    float* out = (float*)d_out;

    float *rv;
    __half *xhi, *xlo, *qkhi, *qklo, *athi, *atlo;
    __half *wqkh, *wqkl, *wvh, *wvl, *woh, *wol, *rth, *rtl;
    __nv_bfloat16 *vhi, *vlo;
    cudaGetSymbolAddress((void**)&rv, g_rv);
    cudaGetSymbolAddress((void**)&xhi, g_x_hi);
    cudaGetSymbolAddress((void**)&xlo, g_x_lo);
    cudaGetSymbolAddress((void**)&qkhi, g_qk_hi);
    cudaGetSymbolAddress((void**)&qklo, g_qk_lo);
    cudaGetSymbolAddress((void**)&athi, g_attn_hi);
    cudaGetSymbolAddress((void**)&atlo, g_attn_lo);
    cudaGetSymbolAddress((void**)&wqkh, g_wqkT_hi);
    cudaGetSymbolAddress((void**)&wqkl, g_wqkT_lo);
    cudaGetSymbolAddress((void**)&wvh, g_wvT_hi);
    cudaGetSymbolAddress((void**)&wvl, g_wvT_lo);
    cudaGetSymbolAddress((void**)&woh, g_woutT_hi);
    cudaGetSymbolAddress((void**)&wol, g_woutT_lo);
    cudaGetSymbolAddress((void**)&rth, g_rotT_hi);
    cudaGetSymbolAddress((void**)&rtl, g_rotT_lo);
    cudaGetSymbolAddress((void**)&vhi, g_v_hi);
    cudaGetSymbolAddress((void**)&vlo, g_v_lo);

    cudaFuncSetAttribute(mma_gemm_h, cudaFuncAttributeMaxDynamicSharedMemorySize, GEMM_SMEM);
    cudaFuncSetAttribute(attn_kernel, cudaFuncAttributeMaxDynamicSharedMemorySize, SMEM_ATT);

    convert_pair_kernel<<<(BT * EMB) / 256, 256>>>(x, xhi, xlo, BT * EMB);
    transpose_pair_kernel<<<dim3(EMB / 32, EMB / 32), dim3(32, 8)>>>(Wqk, wqkh, wqkl, EMB, EMB);
    transpose_pair_kernel<<<dim3(EMB / 32, EMB / 32), dim3(32, 8)>>>(Wv, wvh, wvl, EMB, EMB);
    transpose_pair_kernel<<<dim3(EMB / 32, EMB / 32), dim3(32, 8)>>>(Wout, woh, wol, EMB, EMB);
    transpose_pair_kernel<<<dim3(512 / 32, DH / 32), dim3(32, 8)>>>(rot, rth, rtl, DH, 512);
    zero_fixn_kernel<<<1, 1>>>();

    // qk = x @ Wqk — fp16 pair out only (rv GEMM + prep inputs)
    mma_gemm_h<<<dim3(EMB / 128, BT / 128, 1), 256, GEMM_SMEM>>>(
        xhi, xlo, wqkh, wqkl, nullptr, nullptr, qkhi, qklo, 0,
        EMB, EMB, EMB, EMB, 0, 0, 1, 0, 0);
    // v = x @ Wv — bf16 pair out only
    mma_gemm_h<<<dim3(EMB / 128, BT / 128, 1), 256, GEMM_SMEM>>>(
        xhi, xlo, wvh, wvl, nullptr, nullptr, (__half*)vhi, (__half*)vlo, 1,
        EMB, EMB, EMB, EMB, 0, 0, 1, 0, 0);
    // rv[bh] = qk_head[bh] @ rot
    mma_gemm_h<<<dim3(512 / 128, T_LEN / 128, BHD), 256, GEMM_SMEM>>>(
        qkhi, qklo, rth, rtl, rv, nullptr, nullptr, nullptr, 0,
        DH, EMB, DH, 512, (long long)T_LEN * EMB, DH, N_HASH, 0, (long long)T_LEN * 512);

    // k-hat pairs + qscale per (token, head)
    prep_qk_kernel<<<BT, 256>>>();

    bucket_kernel<<<(BHD * HT) / 256, 256>>>();
    fixup_kernel<<<256, 256>>>(x, Wqk, rot);
    segcount_kernel<<<(BHD * N_HASH * NSEG) / 8, 256>>>();
    sumcnt_kernel<<<(BHD * NBTOT) / 256, 256>>>();
    scan_kernel<<<BHD, NBTOT>>>();
    segbase_kernel<<<BHD, NBTOT>>>();
    scatter_seg_kernel<<<(BHD * N_HASH * NSEG) / 8, 256>>>();

    attn_kernel<<<dim3(NCHUNK, BHD), 256, SMEM_ATT>>>(pm);

    combine_kernel<<<(BHD * T_LEN) / 8, 256>>>();

    // out = attn @ Wout + bout
    mma_gemm_h<<<dim3(EMB / 128, BT / 128, 1), 256, GEMM_SMEM>>>(
        athi, atlo, woh, wol, out, bout, nullptr, nullptr, 0,
        EMB, EMB, EMB, EMB, 0, 0, 1, 0, 0);
}

// round 17
// speedup vs baseline: 1.0616x; 1.0616x over previous
#include <cuda_runtime.h>
#include <cuda_bf16.h>
#include <cuda_fp16.h>
#include <cstdint>
#include <math.h>

#define T_LEN   8192
#define B_SZ    2
#define N_HEADS 8
#define DH      128
#define EMB     1024
#define BHD     16          // B * HEADS
#define N_HASH  8
#define NB      128         // buckets per hash
#define NBTOT   1024        // N_HASH * NB
#define BUCKETSZ 64
#define NCHUNK  1024        // per bh
#define HT      65536       // N_HASH * T
#define BT      16384       // B * T
#define QSCALE  0.08838834764831843f
#define FIX_CAP (1 << 20)
#define MARGIN_TH 4e-3f
#define SEGSZ   512
#define NSEG    16          // T_LEN / SEGSZ

// ----------------------------- scratch (static device memory; no allocs) ---
__device__ __half g_x_hi[(size_t)BT * EMB];
__device__ __half g_x_lo[(size_t)BT * EMB];
__device__ __half g_qk_hi[(size_t)BT * EMB];        // fp16 pairs (rv GEMM + prep)
__device__ __half g_qk_lo[(size_t)BT * EMB];
__device__ __nv_bfloat16 g_k_hi[(size_t)BT * EMB];  // normalized k (attention)
__device__ __nv_bfloat16 g_k_lo[(size_t)BT * EMB];
__device__ float g_qscale[(size_t)BT * N_HEADS];    // QSCALE * ||qk_row||
__device__ __nv_bfloat16 g_v_hi[(size_t)BT * EMB];  // v pairs (from GEMM epilogue)
__device__ __nv_bfloat16 g_v_lo[(size_t)BT * EMB];
__device__ __half g_attn_hi[(size_t)BT * EMB];
__device__ __half g_attn_lo[(size_t)BT * EMB];
__device__ __half g_wqkT_hi[EMB * EMB];
__device__ __half g_wqkT_lo[EMB * EMB];
__device__ __half g_wvT_hi[EMB * EMB];
__device__ __half g_wvT_lo[EMB * EMB];
__device__ __half g_woutT_hi[EMB * EMB];
__device__ __half g_woutT_lo[EMB * EMB];
__device__ __half g_rotT_hi[512 * DH];
__device__ __half g_rotT_lo[512 * DH];
__device__ float g_rv[(size_t)BHD * T_LEN * 512];
__device__ int   g_buckets[(size_t)BHD * HT];
__device__ int   g_segcnt[BHD * N_HASH * NSEG * NB];   // 1 MB
__device__ int   g_segbase[BHD * N_HASH * NSEG * NB];  // 1 MB
__device__ int   g_st[(size_t)BHD * HT];
__device__ int   g_undo[(size_t)BHD * HT];
__device__ int   g_fixn;
__device__ int   g_fixlist[FIX_CAP];
__device__ __half g_so_h[(size_t)BHD * HT * DH];    // fp16 attention outputs
__device__ float g_slog[(size_t)BHD * HT];

// ----------------------------- cp.async helpers -----------------------------
__device__ __forceinline__ void cp_async16(uint32_t dst, const void* src) {
    asm volatile("cp.async.ca.shared.global [%0], [%1], 16;" :: "r"(dst), "l"(src));
}
#define CP_COMMIT() asm volatile("cp.async.commit_group;" ::: "memory")
#define CP_WAIT(n)  asm volatile("cp.async.wait_group %0;" :: "n"(n) : "memory")

// ----------------------------- mma helpers (portable PTX, sm_80+) ----------
__device__ __forceinline__ uint32_t smem_u32(const void* p) {
    uint32_t a;
    asm("{ .reg .u64 t; cvta.to.shared.u64 t, %1; cvt.u32.u64 %0, t; }" : "=r"(a) : "l"(p));
    return a;
}
__device__ __forceinline__ void ldm_x4(uint32_t* r, uint32_t addr) {
    asm volatile("ldmatrix.sync.aligned.m8n8.x4.shared.b16 {%0,%1,%2,%3}, [%4];"
        : "=r"(r[0]), "=r"(r[1]), "=r"(r[2]), "=r"(r[3]) : "r"(addr));
}
__device__ __forceinline__ void ldm_x4_t(uint32_t* r, uint32_t addr) {
    asm volatile("ldmatrix.sync.aligned.m8n8.x4.trans.shared.b16 {%0,%1,%2,%3}, [%4];"
        : "=r"(r[0]), "=r"(r[1]), "=r"(r[2]), "=r"(r[3]) : "r"(addr));
}
__device__ __forceinline__ void ldm_x2(uint32_t* r, uint32_t addr) {
    asm volatile("ldmatrix.sync.aligned.m8n8.x2.shared.b16 {%0,%1}, [%2];"
        : "=r"(r[0]), "=r"(r[1]) : "r"(addr));
}
__device__ __forceinline__ void mma16816(float* d, const uint32_t* a, const uint32_t* b) {
    asm volatile("mma.sync.aligned.m16n8k16.row.col.f32.bf16.bf16.f32 "
        "{%0,%1,%2,%3}, {%4,%5,%6,%7}, {%8,%9}, {%0,%1,%2,%3};"
        : "+f"(d[0]), "+f"(d[1]), "+f"(d[2]), "+f"(d[3])
        : "r"(a[0]), "r"(a[1]), "r"(a[2]), "r"(a[3]), "r"(b[0]), "r"(b[1]));
}
__device__ __forceinline__ void mma16816h(float* d, const uint32_t* a, const uint32_t* b) {
    asm volatile("mma.sync.aligned.m16n8k16.row.col.f32.f16.f16.f32 "
        "{%0,%1,%2,%3}, {%4,%5,%6,%7}, {%8,%9}, {%0,%1,%2,%3};"
        : "+f"(d[0]), "+f"(d[1]), "+f"(d[2]), "+f"(d[3])
        : "r"(a[0]), "r"(a[1]), "r"(a[2]), "r"(a[3]), "r"(b[0]), "r"(b[1]));
}
__device__ __forceinline__ uint32_t packbf2(float x, float y) {
    __nv_bfloat162 p(__float2bfloat16_rn(x), __float2bfloat16_rn(y));
    return *(uint32_t*)&p;
}

// ----------------------------- fp16-split tensor-core GEMM (pipelined) ------
// C[M,N] = A[M,K] @ B^T (B stored [N][K]); A,B fp16 (hi,lo) pairs, 3 terms.
// 2-stage cp.async double buffering; BK=64; 128KB dynamic smem. (proven cfg)
// Pair output: bf16pair=0 -> fp16 pairs; 1 -> bf16 pairs. C may be null.
#define SA_HI 0
#define SA_LO 16384
#define SB_HI 32768
#define SB_LO 49152
#define STAGE_STRIDE 65536
#define GEMM_SMEM 131072

__global__ void __launch_bounds__(256) mma_gemm_h(
    const __half* __restrict__ Ahi, const __half* __restrict__ Alo,
    const __half* __restrict__ Bhi, const __half* __restrict__ Blo,
    float* __restrict__ C, const float* __restrict__ bias,
    __half* __restrict__ Chi, __half* __restrict__ Clo, int bf16pair,
    int K, int lda, int ldb, int ldc,
    long long sAouter, long long sAinner, int innerDiv,
    long long sB, long long sC)
{
    extern __shared__ char sm[];
    uint32_t sb = smem_u32(sm);
    int tid = threadIdx.x, lane = tid & 31, wid = tid >> 5;
    int wm = wid & 1, wn = wid >> 1;

    long long z = blockIdx.z;
    size_t aoff = (size_t)((z / innerDiv) * sAouter + (z % innerDiv) * sAinner);
    const __half* Ah = Ahi + aoff;
    const __half* Al = Alo + aoff;
    const __half* Bh = Bhi + (size_t)(z * sB);
    const __half* Bl = Blo + (size_t)(z * sB);
    int m0 = blockIdx.y * 128, n0 = blockIdx.x * 128;

    float acc[4][4][4];
#pragma unroll
    for (int mt = 0; mt < 4; mt++)
#pragma unroll
        for (int nt = 0; nt < 4; nt++)
#pragma unroll
            for (int i = 0; i < 4; i++) acc[mt][nt][i] = 0.f;

    int nch = K >> 6;

    auto issue = [&](int ch) {
        int k0 = ch << 6;
        uint32_t stg = sb + (uint32_t)((ch & 1) * STAGE_STRIDE);
        const __half* Abh = Ah + (size_t)m0 * lda + k0;
        const __half* Abl = Al + (size_t)m0 * lda + k0;
        const __half* Bbh = Bh + (size_t)n0 * ldb + k0;
        const __half* Bbl = Bl + (size_t)n0 * ldb + k0;
#pragma unroll
        for (int i = 0; i < 4; i++) {
            int idx = tid + (i << 8);
            int row = idx >> 3, seg = idx & 7;
            uint32_t off = (uint32_t)((row << 7) + (seg << 4));
            uint32_t sw = off ^ ((off >> 3) & 0x70);
            cp_async16(stg + SA_HI + sw, Abh + (size_t)row * lda + (seg << 3));
            cp_async16(stg + SA_LO + sw, Abl + (size_t)row * lda + (seg << 3));
            cp_async16(stg + SB_HI + sw, Bbh + (size_t)row * ldb + (seg << 3));
            cp_async16(stg + SB_LO + sw, Bbl + (size_t)row * ldb + (seg << 3));
        }
        CP_COMMIT();
    };

    issue(0);
    for (int ch = 0; ch < nch; ch++) {
        if (ch + 1 < nch) {
            issue(ch + 1);
            CP_WAIT(1);
        } else {
            CP_WAIT(0);
        }
        __syncthreads();
        uint32_t stg = sb + (uint32_t)((ch & 1) * STAGE_STRIDE);
#pragma unroll
        for (int kk = 0; kk < 4; kk++) {
            uint32_t afh[4][4], afl[4][4];
#pragma unroll
            for (int mt = 0; mt < 4; mt++) {
                int row = wm * 64 + mt * 16 + (lane & 15);
                uint32_t off = (uint32_t)((row << 7) + (kk << 5) + ((lane >> 4) << 4));
                uint32_t sw = off ^ ((off >> 3) & 0x70);
                ldm_x4(afh[mt], stg + SA_HI + sw);
                ldm_x4(afl[mt], stg + SA_LO + sw);
            }
            uint32_t bfh[4][2], bfl[4][2];
#pragma unroll
            for (int nt = 0; nt < 4; nt++) {
                int row = wn * 32 + nt * 8 + (lane & 7);
                uint32_t off = (uint32_t)((row << 7) + (kk << 5) + (((lane >> 3) & 1) << 4));
                uint32_t sw = off ^ ((off >> 3) & 0x70);
                ldm_x2(bfh[nt], stg + SB_HI + sw);
                ldm_x2(bfl[nt], stg + SB_LO + sw);
            }
#pragma unroll
            for (int mt = 0; mt < 4; mt++)
#pragma unroll
                for (int nt = 0; nt < 4; nt++) {
                    mma16816h(acc[mt][nt], afh[mt], bfh[nt]);
                    mma16816h(acc[mt][nt], afh[mt], bfl[nt]);
                    mma16816h(acc[mt][nt], afl[mt], bfh[nt]);
                }
        }
        __syncthreads();
    }

    float* Cb = C ? (C + (size_t)(z * sC)) : nullptr;
#pragma unroll
    for (int mt = 0; mt < 4; mt++) {
#pragma unroll
        for (int nt = 0; nt < 4; nt++) {
            int c = n0 + wn * 32 + nt * 8 + ((lane & 3) << 1);
#pragma unroll
            for (int hf = 0; hf < 2; hf++) {
                int r = m0 + wm * 64 + mt * 16 + (lane >> 2) + hf * 8;
                float v0 = acc[mt][nt][hf * 2 + 0];
                float v1 = acc[mt][nt][hf * 2 + 1];
                if (bias) { v0 += bias[c]; v1 += bias[c + 1]; }
                size_t off = (size_t)r * ldc + c;
                if (Cb) *(float2*)(Cb + off) = make_float2(v0, v1);
                if (Chi) {
                    if (bf16pair) {
                        float h0 = __bfloat162float(__float2bfloat16_rn(v0));
                        float h1 = __bfloat162float(__float2bfloat16_rn(v1));
                        *(uint32_t*)(Chi + off) = packbf2(v0, v1);
                        *(uint32_t*)(Clo + off) = packbf2(v0 - h0, v1 - h1);
                    } else {
                        __half h0 = __float2half_rn(v0);
                        __half h1 = __float2half_rn(v1);
                        *(__half2*)(Chi + off) = __half2(h0, h1);
                        *(__half2*)(Clo + off) = __half2(
                            __float2half_rn(v0 - __half2float(h0)),
                            __float2half_rn(v1 - __half2float(h1)));
                    }
                }
            }
        }
    }
}

// ----------------------------- conversions ----------------------------------
__global__ void convert_pair_kernel(const float* __restrict__ src,
                                    __half* __restrict__ hi,
                                    __half* __restrict__ lo, int n)
{
    int i = blockIdx.x * 256 + threadIdx.x;
    if (i == 0) g_fixn = 0;
    if (i < n) {
        float v = src[i];
        __half h = __float2half_rn(v);
        hi[i] = h;
        lo[i] = __float2half_rn(v - __half2float(h));
    }
}

__global__ void transpose_pair_kernel(const float* __restrict__ src,
                                      __half* __restrict__ dhi,
                                      __half* __restrict__ dlo, int R, int C)
{
    __shared__ float t[32][33];
    int c0 = blockIdx.x * 32, r0 = blockIdx.y * 32;
    int x = threadIdx.x, y = threadIdx.y;
    for (int i = 0; i < 32; i += 8)
        t[y + i][x] = src[(size_t)(r0 + y + i) * C + c0 + x];
    __syncthreads();
    for (int i = 0; i < 32; i += 8) {
        float v = t[x][y + i];
        __half h = __float2half_rn(v);
        size_t o = (size_t)(c0 + y + i) * R + r0 + x;
        dhi[o] = h;
        dlo[o] = __float2half_rn(v - __half2float(h));
    }
}

// ----------------------------- k-hat + qscale precompute --------------------
__global__ void prep_qk_kernel()
{
    int gw = (blockIdx.x * 256 + threadIdx.x) >> 5;    // 0..BT*8-1
    int lane = threadIdx.x & 31;
    int h = gw & 7;
    int bt = gw >> 3;
    size_t base = (size_t)bt * EMB + h * DH;
    uint2 uh = *(const uint2*)(g_qk_hi + base + lane * 4);
    uint2 ul = *(const uint2*)(g_qk_lo + base + lane * 4);
    __half2 h01 = *(__half2*)&uh.x, h23 = *(__half2*)&uh.y;
    __half2 l01 = *(__half2*)&ul.x, l23 = *(__half2*)&ul.y;
    float v0 = __half2float(h01.x) + __half2float(l01.x);
    float v1 = __half2float(h01.y) + __half2float(l01.y);
    float v2 = __half2float(h23.x) + __half2float(l23.x);
    float v3 = __half2float(h23.y) + __half2float(l23.y);
    float ss = v0 * v0 + v1 * v1 + v2 * v2 + v3 * v3;
#pragma unroll
    for (int o = 16; o > 0; o >>= 1) ss += __shfl_xor_sync(0xffffffffu, ss, o);
    float sq = sqrtf(fmaxf(ss, 1e-12f));
    float rn = 1.0f / sq;
    float k0v = v0 * rn, k1v = v1 * rn, k2v = v2 * rn, k3v = v3 * rn;
    float kh0 = __bfloat162float(__float2bfloat16_rn(k0v));
    float kh1 = __bfloat162float(__float2bfloat16_rn(k1v));
    float kh2 = __bfloat162float(__float2bfloat16_rn(k2v));
    float kh3 = __bfloat162float(__float2bfloat16_rn(k3v));
    size_t e = base + lane * 4;
    *(uint2*)(g_k_hi + e) = make_uint2(packbf2(k0v, k1v), packbf2(k2v, k3v));
    *(uint2*)(g_k_lo + e) = make_uint2(packbf2(k0v - kh0, k1v - kh1), packbf2(k2v - kh2, k3v - kh3));
    if (lane == 0) g_qscale[(size_t)bt * N_HEADS + h] = QSCALE * sq;
}

// ----------------------------- bucket argmax + margin guard -----------------
__global__ void bucket_kernel()
{
    int idx = blockIdx.x * 256 + threadIdx.x;
    int h = idx & 7;
    int t = (idx >> 3) & (T_LEN - 1);
    int bh = idx >> 16;
    const float4* p = (const float4*)(g_rv + ((size_t)bh * T_LEN + t) * 512 + h * 64);
    float max1 = -1e30f, max2 = -1e30f, min1 = 1e30f, min2 = 1e30f;
    int imax = 0, imin = 0;
#pragma unroll
    for (int i = 0; i < 16; i++) {
        float4 q = p[i];
        float vv[4] = {q.x, q.y, q.z, q.w};
#pragma unroll
        for (int c = 0; c < 4; c++) {
            int j = i * 4 + c;
            float v = vv[c];
            if (v > max1) { max2 = max1; max1 = v; imax = j; }
            else if (v > max2) max2 = v;
            if (v < min1) { min2 = min1; min1 = v; imin = j; }
            else if (v < min2) min2 = v;
        }
    }
    float best, second;
    int bi;
    if (max1 >= -min1) { best = max1; bi = imax; second = fmaxf(max2, -min1); }
    else               { best = -min1; bi = 64 + imin; second = fmaxf(max1, -min2); }
    g_buckets[(size_t)bh * HT + (size_t)h * T_LEN + t] = bi + h * NB;
    if (best - second < MARGIN_TH) {
        int slot = atomicAdd(&g_fixn, 1);
        if (slot < FIX_CAP)
            g_fixlist[slot] = (bh << 16) | (h * T_LEN + t);
    }
}

// full exact recompute of flagged rows (sequential fp32 from x, Wqk, rot)
__global__ void fixup_kernel(const float* __restrict__ x,
                             const float* __restrict__ Wqk,
                             const float* __restrict__ rot)
{
    __shared__ float qrow_s[8][128];
    int wslot = threadIdx.x >> 5;
    int lane = threadIdx.x & 31;
    int gw = blockIdx.x * 8 + wslot;
    int nwarps = gridDim.x * 8;
    int n = g_fixn;
    if (n > FIX_CAP) n = FIX_CAP;
    for (int e = gw; e < n; e += nwarps) {
        int ent = g_fixlist[e];
        int bh = ent >> 16;
        int ht = ent & 65535;
        int h = ht >> 13, t = ht & (T_LEN - 1);
        int b = bh >> 3, hh = bh & 7;
        const float* xrow = x + (size_t)(b * T_LEN + t) * EMB;
        float a0 = 0.f, a1 = 0.f, a2 = 0.f, a3 = 0.f;
        for (int k = 0; k < EMB; k++) {
            float xv = xrow[k];
            const float* wr = Wqk + (size_t)k * EMB + hh * DH;
            a0 = fmaf(xv, wr[lane], a0);
            a1 = fmaf(xv, wr[lane + 32], a1);
            a2 = fmaf(xv, wr[lane + 64], a2);
            a3 = fmaf(xv, wr[lane + 96], a3);
        }
        qrow_s[wslot][lane] = a0;
        qrow_s[wslot][lane + 32] = a1;
        qrow_s[wslot][lane + 64] = a2;
        qrow_s[wslot][lane + 96] = a3;
        __syncwarp();
        int c1 = lane, c2 = lane + 32;
        float r1 = 0.f, r2 = 0.f;
        for (int k = 0; k < DH; k++) {
            float a = qrow_s[wslot][k];
            const float* rp = rot + ((size_t)k * 8 + h) * 64;
            r1 = fmaf(a, rp[c1], r1);
            r2 = fmaf(a, rp[c2], r2);
        }
        float best = r1; int bi = c1;
        if (r2 > best)  { best = r2;  bi = c2; }
        if (-r1 > best) { best = -r1; bi = 64 + c1; }
        if (-r2 > best) { best = -r2; bi = 64 + c2; }
#pragma unroll
        for (int o = 16; o > 0; o >>= 1) {
            float ov = __shfl_xor_sync(0xffffffffu, best, o);
            int oi = __shfl_xor_sync(0xffffffffu, bi, o);
            if (ov > best || (ov == best && oi < bi)) { best = ov; bi = oi; }
        }
        if (lane == 0)
            g_buckets[(size_t)bh * HT + (size_t)h * T_LEN + t] = bi + h * NB;
        __syncwarp();
    }
}

// ----------------------------- segmented stable counting sort ---------------
// per-(bh, h, 512-token segment) histogram (one warp each)
__global__ void segcount_kernel()
{
    __shared__ int hist[8][NB];
    int w = threadIdx.x >> 5, lane = threadIdx.x & 31;
    int gw = blockIdx.x * 8 + w;               // 0..BHD*8*NSEG-1
    int seg = gw & (NSEG - 1);
    int h = (gw >> 4) & 7;
    int bh = gw >> 7;
    for (int i = lane; i < NB; i += 32) hist[w][i] = 0;
    __syncwarp();
    const int* bk = g_buckets + (size_t)bh * HT + (size_t)h * T_LEN + seg * SEGSZ;
    for (int t0 = 0; t0 < SEGSZ; t0 += 32)
        atomicAdd(&hist[w][bk[t0 + lane] - h * NB], 1);
    __syncwarp();
    int* dst = g_segcnt + (((bh * 8 + h) * NSEG) + seg) * NB;
    for (int i = lane; i < NB; i += 32) dst[i] = hist[w][i];
}

// fused: per-bucket seg-sum + block-wide exclusive scan + per-seg bases
__global__ void sortmeta_kernel()
{
    __shared__ int s[NBTOT];
    int bh = blockIdx.x, gb = threadIdx.x;     // gb = 0..1023
    int h = gb >> 7, b = gb & 127;
    const int* sc = g_segcnt + ((bh * 8 + h) * NSEG) * NB + b;
    int cnt[NSEG];
    int tot = 0;
#pragma unroll
    for (int i = 0; i < NSEG; i++) { cnt[i] = sc[i * NB]; tot += cnt[i]; }
    s[gb] = tot;
    __syncthreads();
    for (int d = 1; d < NBTOT; d <<= 1) {
        int v = (gb >= d) ? s[gb - d] : 0;
        __syncthreads();
        s[gb] += v;
        __syncthreads();
    }
    int base = s[gb] - tot;                    // exclusive prefix
    int* sbp = g_segbase + ((bh * 8 + h) * NSEG) * NB + b;
#pragma unroll
    for (int i = 0; i < NSEG; i++) { sbp[i * NB] = base; base += cnt[i]; }
}

// parallel stable scatter: one warp per (bh, h, segment)
__global__ void scatter_seg_kernel()
{
    __shared__ int cnt[8][NB];
    int w = threadIdx.x >> 5, lane = threadIdx.x & 31;
    int gw = blockIdx.x * 8 + w;
    int seg = gw & (NSEG - 1);
    int h = (gw >> 4) & 7;
    int bh = gw >> 7;
    const int* sbp = g_segbase + (((bh * 8 + h) * NSEG) + seg) * NB;
    for (int i = lane; i < NB; i += 32) cnt[w][i] = sbp[i];
    __syncwarp();
    const int* bk = g_buckets + (size_t)bh * HT + (size_t)h * T_LEN;
    int* stp = g_st + (size_t)bh * HT;
    int* unp = g_undo + (size_t)bh * HT + (size_t)h * T_LEN;
    int tb = seg * SEGSZ;
    for (int t0 = tb; t0 < tb + SEGSZ; t0 += 32) {
        int t = t0 + lane;
        int b = bk[t] - h * NB;
        unsigned mask = __match_any_sync(0xffffffffu, b);
        int lead = __ffs(mask) - 1;
        int pre = __popc(mask & ((1u << lane) - 1u));
        int base = 0;
        if (lane == lead) base = cnt[w][b];
        base = __shfl_sync(0xffffffffu, base, lead);
        int rnk = base + pre;
        if (lane == lead) cnt[w][b] = base + __popc(mask);
        stp[rnk] = t;
        unp[t] = rnk;
        __syncwarp();
    }
}

// ----------------------------- tensor-core chunked attention ----------------
#define PT  136
#define OFF_KV_HI 0
#define OFF_KV_LO 34816
#define OFF_P_HI  69632
#define OFF_P_LO  87040
#define OFF_REDM  104448
#define OFF_REDS  104960
#define OFF_POS   105472
#define OFF_PAD   105984
#define OFF_SCL   106496
#define SMEM_ATT  106752

__global__ void __launch_bounds__(256, 2) attn_kernel(const unsigned char* __restrict__ pm)
{
    extern __shared__ char sm[];
    uint32_t sb = smem_u32(sm);
    __nv_bfloat16* phi = (__nv_bfloat16*)(sm + OFF_P_HI);
    __nv_bfloat16* plo = (__nv_bfloat16*)(sm + OFF_P_LO);
    float* redM = (float*)(sm + OFF_REDM);
    float* redS = (float*)(sm + OFF_REDS);
    int* posk = (int*)(sm + OFF_POS);
    int* padk = (int*)(sm + OFF_PAD);
    float* sclb = (float*)(sm + OFF_SCL);

    int bh = blockIdx.y, c = blockIdx.x;
    int b = bh >> 3, h = bh & 7;
    int tid = threadIdx.x, lane = tid & 31, wid = tid >> 5;

    if (tid < 128) {
        int j = tid;
        int cprev = (c == 0) ? (NCHUNK - 1) : (c - 1);
        int slot = (j < BUCKETSZ) ? c * BUCKETSZ + j : cprev * BUCKETSZ + (j - BUCKETSZ);
        int pos = g_st[(size_t)bh * HT + slot];
        posk[j] = pos;
        padk[j] = pm[b * T_LEN + pos] ? 1 : 0;
        if (j < 64) sclb[j] = g_qscale[(size_t)(b * T_LEN + pos) * N_HEADS + h];
    }
    __syncthreads();

    // phase 1: cp.async gather of k-hat pairs (128 rows)
    for (int i = tid; i < 2048; i += 256) {
        int r = i >> 4, ck = i & 15;
        int pos = posk[r];
        size_t so = (size_t)(b * T_LEN + pos) * EMB + h * DH + (ck << 3);
        uint32_t d = (uint32_t)((r * PT + (ck << 3)) * 2);
        cp_async16(sb + OFF_KV_HI + d, g_k_hi + so);
        cp_async16(sb + OFF_KV_LO + d, g_k_lo + so);
    }
    CP_COMMIT();
    CP_WAIT(0);
    __syncthreads();

    // phase 2: S[64][128] = (k-hat_q @ k-hat_kv^T) * scale_q
    int mt = wid & 3, nh = wid >> 2;
    float cS[8][4];
#pragma unroll
    for (int i = 0; i < 8; i++)
#pragma unroll
        for (int j = 0; j < 4; j++) cS[i][j] = 0.f;
    {
        uint32_t g = lane >> 3, i2 = lane & 7;
#pragma unroll
        for (int ks = 0; ks < 8; ks++) {
            int k0 = ks * 16;
            uint32_t ah[4], al[4];
            uint32_t aoff = (uint32_t)(((mt * 16 + (lane & 15)) * PT + k0 + ((lane >> 4) << 3)) * 2);
            ldm_x4(ah, sb + OFF_KV_HI + aoff);
            ldm_x4(al, sb + OFF_KV_LO + aoff);
#pragma unroll
            for (int np = 0; np < 4; np++) {
                int n0 = nh * 64 + np * 16;
                uint32_t boff = (uint32_t)(((n0 + ((g >> 1) << 3) + i2) * PT + k0 + ((g & 1) << 3)) * 2);
                uint32_t bh4[4], bl4[4];
                ldm_x4(bh4, sb + OFF_KV_HI + boff);
                ldm_x4(bl4, sb + OFF_KV_LO + boff);
                mma16816(cS[np * 2], ah, bh4);
                mma16816(cS[np * 2], ah, bl4);
                mma16816(cS[np * 2], al, bh4);
                mma16816(cS[np * 2 + 1], ah, bh4 + 2);
                mma16816(cS[np * 2 + 1], ah, bl4 + 2);
                mma16816(cS[np * 2 + 1], al, bh4 + 2);
            }
        }
    }

    int q0 = mt * 16 + (lane >> 2);
    {
        float scl0 = sclb[q0], scl1 = sclb[q0 + 8];
        int pq0 = posk[q0], pq1 = posk[q0 + 8];
#pragma unroll
        for (int t8 = 0; t8 < 8; t8++) {
            int kvb = nh * 64 + t8 * 8 + ((lane & 3) << 1);
#pragma unroll
            for (int e = 0; e < 2; e++) {
                int kv = kvb + e;
                int pk = posk[kv], pd = padk[kv];
                float s0 = cS[t8][e] * scl0;
                float s1 = cS[t8][2 + e] * scl1;
                cS[t8][e]     = (pq0 == pk) ? -1e5f : (pd ? -1e9f : s0);
                cS[t8][2 + e] = (pq1 == pk) ? -1e5f : (pd ? -1e9f : s1);
            }
        }
    }

    // phase 3: softmax via e = exp(s - M); scale by 1/Z in the PV epilogue
    float rZA, rZB;
    {
        float mA = -1e30f, mB = -1e30f;
#pragma unroll
        for (int t8 = 0; t8 < 8; t8++) {
            mA = fmaxf(mA, fmaxf(cS[t8][0], cS[t8][1]));
            mB = fmaxf(mB, fmaxf(cS[t8][2], cS[t8][3]));
        }
        mA = fmaxf(mA, __shfl_xor_sync(0xffffffffu, mA, 1));
        mA = fmaxf(mA, __shfl_xor_sync(0xffffffffu, mA, 2));
        mB = fmaxf(mB, __shfl_xor_sync(0xffffffffu, mB, 1));
        mB = fmaxf(mB, __shfl_xor_sync(0xffffffffu, mB, 2));
        if ((lane & 3) == 0) {
            redM[q0 * 2 + nh] = mA;
            redM[(q0 + 8) * 2 + nh] = mB;
        }
        __syncthreads();       // all KV-buffer reads complete block-wide

        // V gather into kv buffers (overlaps exp below)
        for (int i = tid; i < 2048; i += 256) {
            int r = i >> 4, ck = i & 15;
            int pos = posk[r];
            size_t so = (size_t)(b * T_LEN + pos) * EMB + h * DH + (ck << 3);
            uint32_t d = (uint32_t)((r * PT + (ck << 3)) * 2);
            cp_async16(sb + OFF_KV_HI + d, g_v_hi + so);
            cp_async16(sb + OFF_KV_LO + d, g_v_lo + so);
        }
        CP_COMMIT();

        float MA = fmaxf(redM[q0 * 2], redM[q0 * 2 + 1]);
        float MB = fmaxf(redM[(q0 + 8) * 2], redM[(q0 + 8) * 2 + 1]);
        float sA = 0.f, sB = 0.f;
#pragma unroll
        for (int t8 = 0; t8 < 8; t8++) {
            int col = nh * 64 + t8 * 8 + ((lane & 3) << 1);
            float eA0 = __expf(cS[t8][0] - MA), eA1 = __expf(cS[t8][1] - MA);
            float eB0 = __expf(cS[t8][2] - MB), eB1 = __expf(cS[t8][3] - MB);
            sA += eA0 + eA1;
            sB += eB0 + eB1;
            float hA0 = __bfloat162float(__float2bfloat16_rn(eA0));
            float hA1 = __bfloat162float(__float2bfloat16_rn(eA1));
            float hB0 = __bfloat162float(__float2bfloat16_rn(eB0));
            float hB1 = __bfloat162float(__float2bfloat16_rn(eB1));
            *(uint32_t*)(phi + q0 * PT + col) = packbf2(eA0, eA1);
            *(uint32_t*)(plo + q0 * PT + col) = packbf2(eA0 - hA0, eA1 - hA1);
            *(uint32_t*)(phi + (q0 + 8) * PT + col) = packbf2(eB0, eB1);
            *(uint32_t*)(plo + (q0 + 8) * PT + col) = packbf2(eB0 - hB0, eB1 - hB1);
        }
        sA += __shfl_xor_sync(0xffffffffu, sA, 1);
        sA += __shfl_xor_sync(0xffffffffu, sA, 2);
        sB += __shfl_xor_sync(0xffffffffu, sB, 1);
        sB += __shfl_xor_sync(0xffffffffu, sB, 2);
        if ((lane & 3) == 0) {
            redS[q0 * 2 + nh] = sA;
            redS[(q0 + 8) * 2 + nh] = sB;
        }
        __syncthreads();
        float ZA = redS[q0 * 2] + redS[q0 * 2 + 1];
        float ZB = redS[(q0 + 8) * 2] + redS[(q0 + 8) * 2 + 1];
        if (nh == 0 && (lane & 3) == 0) {
            g_slog[(size_t)bh * HT + c * BUCKETSZ + q0] = MA + __logf(ZA);
            g_slog[(size_t)bh * HT + c * BUCKETSZ + q0 + 8] = MB + __logf(ZB);
        }
        rZA = 1.0f / ZA;
        rZB = 1.0f / ZB;
    }
    CP_WAIT(0);          // V resident
    __syncthreads();     // e writes visible block-wide

    // phase 4: O[64][128] = (E @ V) / Z
    {
        int dh2 = nh;
        float cO[8][4];
#pragma unroll
        for (int i = 0; i < 8; i++)
#pragma unroll
            for (int j = 0; j < 4; j++) cO[i][j] = 0.f;

        uint32_t g = lane >> 3, i2 = lane & 7;
#pragma unroll
        for (int ks = 0; ks < 8; ks++) {
            int k0 = ks * 16;
            uint32_t ah[4], al[4];
            uint32_t aoff = (uint32_t)(((mt * 16 + (lane & 15)) * PT + k0 + ((lane >> 4) << 3)) * 2);
            ldm_x4(ah, sb + OFF_P_HI + aoff);
            ldm_x4(al, sb + OFF_P_LO + aoff);
#pragma unroll
            for (int dp = 0; dp < 4; dp++) {
                int d0 = dh2 * 64 + dp * 16;
                uint32_t boff = (uint32_t)(((k0 + ((g & 1) << 3) + i2) * PT + d0 + ((g >> 1) << 3)) * 2);
                uint32_t bh4[4], bl4[4];
                ldm_x4_t(bh4, sb + OFF_KV_HI + boff);
                ldm_x4_t(bl4, sb + OFF_KV_LO + boff);
                mma16816(cO[dp * 2], ah, bh4);
                mma16816(cO[dp * 2], ah, bl4);
                mma16816(cO[dp * 2], al, bh4);
                mma16816(cO[dp * 2 + 1], ah, bh4 + 2);
                mma16816(cO[dp * 2 + 1], ah, bl4 + 2);
                mma16816(cO[dp * 2 + 1], al, bh4 + 2);
            }
        }
        __half* base0 = g_so_h + ((size_t)bh * HT + c * BUCKETSZ + q0) * DH;
        __half* base1 = g_so_h + ((size_t)bh * HT + c * BUCKETSZ + q0 + 8) * DH;
#pragma unroll
        for (int t8 = 0; t8 < 8; t8++) {
            int d = dh2 * 64 + t8 * 8 + ((lane & 3) << 1);
            *(__half2*)(base0 + d) = __floats2half2_rn(cO[t8][0] * rZA, cO[t8][1] * rZA);
            *(__half2*)(base1 + d) = __floats2half2_rn(cO[t8][2] * rZB, cO[t8][3] * rZB);
        }
    }
}

// ----------------------------- combine hash rounds --------------------------
__global__ void combine_kernel()
{
    int gw = (blockIdx.x * 256 + threadIdx.x) >> 5;
    int lane = threadIdx.x & 31;
    int bh = gw >> 13;
    int pos = gw & (T_LEN - 1);
    int b = bh >> 3, hh = bh & 7;

    int s = 0;
    float l = -1e30f;
    if (lane < N_HASH) {
        s = g_undo[(size_t)bh * HT + (size_t)lane * T_LEN + pos];
        l = g_slog[(size_t)bh * HT + s];
    }
    float m = l;
#pragma unroll
    for (int o = 16; o > 0; o >>= 1) m = fmaxf(m, __shfl_xor_sync(0xffffffffu, m, o));
    float e = (lane < N_HASH) ? __expf(l - m) : 0.f;
    float Z = e;
#pragma unroll
    for (int o = 16; o > 0; o >>= 1) Z += __shfl_xor_sync(0xffffffffu, Z, o);

    float4 acc = make_float4(0.f, 0.f, 0.f, 0.f);
#pragma unroll
    for (int h2 = 0; h2 < N_HASH; h2++) {
        int sh = __shfl_sync(0xffffffffu, s, h2);
        float wv = __shfl_sync(0xffffffffu, e, h2) / Z;
        const __half2* row = (const __half2*)(g_so_h + ((size_t)bh * HT + sh) * DH);
        __half2 p0 = row[lane * 2], p1 = row[lane * 2 + 1];
        float2 f0 = __half22float2(p0), f1 = __half22float2(p1);
        acc.x = fmaf(wv, f0.x, acc.x);
        acc.y = fmaf(wv, f0.y, acc.y);
        acc.z = fmaf(wv, f1.x, acc.z);
        acc.w = fmaf(wv, f1.y, acc.w);
    }
    size_t off = ((size_t)(b * T_LEN + pos)) * EMB + hh * DH + lane * 4;
    float fv[4] = {acc.x, acc.y, acc.z, acc.w};
    __half hi[4]; float lo[4];
#pragma unroll
    for (int u = 0; u < 4; u++) { hi[u] = __float2half_rn(fv[u]); lo[u] = fv[u] - __half2float(hi[u]); }
    ((__half2*)(g_attn_hi + off))[0] = __half2(hi[0], hi[1]);
    ((__half2*)(g_attn_hi + off))[1] = __half2(hi[2], hi[3]);
    ((__half2*)(g_attn_lo + off))[0] = __half2(__float2half_rn(lo[0]), __float2half_rn(lo[1]));
    ((__half2*)(g_attn_lo + off))[1] = __half2(__float2half_rn(lo[2]), __float2half_rn(lo[3]));
}

// ----------------------------- launcher -------------------------------------
extern "C" void kernel_launch(void* const* d_in, const int* in_sizes, int n_in,
                              void* d_out, int out_size)
{
    const float* x = (const float*)d_in[0];
    const unsigned char* pm = (const unsigned char*)d_in[1];
    const float* rot = (const float*)d_in[2];
    const float* Wqk = (const float*)d_in[3];
    const float* Wv = (const float*)d_in[4];
    const float* Wout = (const float*)d_in[5];
    const float* bout = (const float*)d_in[6];
    float* out = (float*)d_out;

    float *rv;
    __half *xhi, *xlo, *qkhi, *qklo, *athi, *atlo;
    __half *wqkh, *wqkl, *wvh, *wvl, *woh, *wol, *rth, *rtl;
    __nv_bfloat16 *vhi, *vlo;
    cudaGetSymbolAddress((void**)&rv, g_rv);
    cudaGetSymbolAddress((void**)&xhi, g_x_hi);
    cudaGetSymbolAddress((void**)&xlo, g_x_lo);
    cudaGetSymbolAddress((void**)&qkhi, g_qk_hi);
    cudaGetSymbolAddress((void**)&qklo, g_qk_lo);
    cudaGetSymbolAddress((void**)&athi, g_attn_hi);
    cudaGetSymbolAddress((void**)&atlo, g_attn_lo);
    cudaGetSymbolAddress((void**)&wqkh, g_wqkT_hi);
    cudaGetSymbolAddress((void**)&wqkl, g_wqkT_lo);
    cudaGetSymbolAddress((void**)&wvh, g_wvT_hi);
    cudaGetSymbolAddress((void**)&wvl, g_wvT_lo);
    cudaGetSymbolAddress((void**)&woh, g_woutT_hi);
    cudaGetSymbolAddress((void**)&wol, g_woutT_lo);
    cudaGetSymbolAddress((void**)&rth, g_rotT_hi);
    cudaGetSymbolAddress((void**)&rtl, g_rotT_lo);
    cudaGetSymbolAddress((void**)&vhi, g_v_hi);
    cudaGetSymbolAddress((void**)&vlo, g_v_lo);

    cudaFuncSetAttribute(mma_gemm_h, cudaFuncAttributeMaxDynamicSharedMemorySize, GEMM_SMEM);
    cudaFuncSetAttribute(attn_kernel, cudaFuncAttributeMaxDynamicSharedMemorySize, SMEM_ATT);

    convert_pair_kernel<<<(BT * EMB) / 256, 256>>>(x, xhi, xlo, BT * EMB);
    transpose_pair_kernel<<<dim3(EMB / 32, EMB / 32), dim3(32, 8)>>>(Wqk, wqkh, wqkl, EMB, EMB);
    transpose_pair_kernel<<<dim3(EMB / 32, EMB / 32), dim3(32, 8)>>>(Wv, wvh, wvl, EMB, EMB);
    transpose_pair_kernel<<<dim3(EMB / 32, EMB / 32), dim3(32, 8)>>>(Wout, woh, wol, EMB, EMB);
    transpose_pair_kernel<<<dim3(512 / 32, DH / 32), dim3(32, 8)>>>(rot, rth, rtl, DH, 512);

    // qk = x @ Wqk — fp16 pair out only (rv GEMM + prep inputs)
    mma_gemm_h<<<dim3(EMB / 128, BT / 128, 1), 256, GEMM_SMEM>>>(
        xhi, xlo, wqkh, wqkl, nullptr, nullptr, qkhi, qklo, 0,
        EMB, EMB, EMB, EMB, 0, 0, 1, 0, 0);
    // v = x @ Wv — bf16 pair out only
    mma_gemm_h<<<dim3(EMB / 128, BT / 128, 1), 256, GEMM_SMEM>>>(
        xhi, xlo, wvh, wvl, nullptr, nullptr, (__half*)vhi, (__half*)vlo, 1,
        EMB, EMB, EMB, EMB, 0, 0, 1, 0, 0);
    // rv[bh] = qk_head[bh] @ rot
    mma_gemm_h<<<dim3(512 / 128, T_LEN / 128, BHD), 256, GEMM_SMEM>>>(
        qkhi, qklo, rth, rtl, rv, nullptr, nullptr, nullptr, 0,
        DH, EMB, DH, 512, (long long)T_LEN * EMB, DH, N_HASH, 0, (long long)T_LEN * 512);

    // k-hat pairs + qscale per (token, head)
    prep_qk_kernel<<<BT, 256>>>();

    bucket_kernel<<<(BHD * HT) / 256, 256>>>();
    fixup_kernel<<<256, 256>>>(x, Wqk, rot);
    segcount_kernel<<<(BHD * N_HASH * NSEG) / 8, 256>>>();
    sortmeta_kernel<<<BHD, NBTOT>>>();
    scatter_seg_kernel<<<(BHD * N_HASH * NSEG) / 8, 256>>>();

    attn_kernel<<<dim3(NCHUNK, BHD), 256, SMEM_ATT>>>(pm);

    combine_kernel<<<(BHD * T_LEN) / 8, 256>>>();

    // out = attn @ Wout + bout
    mma_gemm_h<<<dim3(EMB / 128, BT / 128, 1), 256, GEMM_SMEM>>>(
        athi, atlo, woh, wol, out, bout, nullptr, nullptr, 0,
        EMB, EMB, EMB, EMB, 0, 0, 1, 0, 0);
}